// round 4
// baseline (speedup 1.0000x reference)
#include <cuda_runtime.h>
#include <math.h>

#define NNODES 100000
#define FIN    512
#define NPATH  1600000
#define NH1    8
#define F1     64      // H1*C1
#define NC2    7
#define NEG    0.2f

// ---------------- scratch (device globals; no allocations) ----------------
static __device__ float g_xp1[NNODES * F1];          // 25.6 MB
static __device__ float g_s1[3][NNODES * NH1];       //  9.6 MB
static __device__ float g_den1[NNODES * NH1];        //  3.2 MB
static __device__ float g_out1[NNODES * F1];         // 25.6 MB
static __device__ float g_xp2[NNODES * 8];           //  3.2 MB (7 + zero pad)
static __device__ float g_s2[3][NNODES];             //  1.2 MB
static __device__ float g_den2[NNODES];              //  0.4 MB
static __device__ float g_logits[NNODES * 8];        //  3.2 MB (7 + pad)
static __device__ int   g_src[NPATH], g_mid[NPATH], g_dst[NPATH];  // 19.2 MB
static __device__ int   g_is64;

__device__ __forceinline__ void red_add_v4(float* p, float a, float b, float c, float d) {
    asm volatile("red.global.add.v4.f32 [%0], {%1,%2,%3,%4};"
                 :: "l"(p), "f"(a), "f"(b), "f"(c), "f"(d) : "memory");
}

// ---------------- 0a: detect path_index dtype -------------------------------
// JAX with x64 disabled silently yields int32 for a requested int64. Interpret
// the first 1024 entries as int64: genuine int64 data has all values in
// [0, NNODES); int32 data read as int64 pairs gives values ~2^32.
__global__ void k_detect(const unsigned long long* __restrict__ pi) {
    __shared__ int bad;
    if (threadIdx.x == 0) bad = 0;
    __syncthreads();
    unsigned long long v = pi[threadIdx.x];           // 1024 threads
    if (v >= (unsigned long long)NNODES) atomicOr(&bad, 1);
    __syncthreads();
    if (threadIdx.x == 0) g_is64 = bad ? 0 : 1;
}

__device__ __forceinline__ int clamp_idx(long long v) {
    int i = (int)v;
    i = i < 0 ? 0 : i;
    return i >= NNODES ? NNODES - 1 : i;
}

// ---------------- 0b: convert path indices to int32 SoA ---------------------
// Clamped: if dtype detection were ever wrong, we get a finite wrong answer
// (diagnosable rel_err) instead of an illegal memory access.
__global__ void k_convert(const void* __restrict__ piv) {
    int i = blockIdx.x * blockDim.x + threadIdx.x;
    if (i >= NPATH) return;
    long long s, m, d;
    if (g_is64) {
        const long long* pi = (const long long*)piv;
        s = pi[i]; m = pi[NPATH + i]; d = pi[2 * NPATH + i];
    } else {
        const int* pi = (const int*)piv;
        s = pi[i]; m = pi[NPATH + i]; d = pi[2 * NPATH + i];
    }
    g_src[i] = clamp_idx(s);
    g_mid[i] = clamp_idx(m);
    g_dst[i] = clamp_idx(d);
}

// ---------------- 0c: zero accumulators (every replay!) ---------------------
__global__ void k_zero() {
    int i = blockIdx.x * blockDim.x + threadIdx.x;
    if (i < NNODES * F1 / 4)  ((float4*)g_out1)[i]   = make_float4(0.f, 0.f, 0.f, 0.f);
    if (i < NNODES * NH1 / 4) ((float4*)g_den1)[i]   = make_float4(0.f, 0.f, 0.f, 0.f);
    if (i < NNODES * 8 / 4)   ((float4*)g_logits)[i] = make_float4(0.f, 0.f, 0.f, 0.f);
    if (i < NNODES / 4)       ((float4*)g_den2)[i]   = make_float4(0.f, 0.f, 0.f, 0.f);
}

// ---------------- 1: xp1 = x @ W1  (fp32 tiled GEMM) -----------------------
// BM=128, BN=64, BK=16, 256 threads, 8x4 microtile per thread.
__global__ void __launch_bounds__(256) k_gemm1(const float* __restrict__ x,
                                               const float* __restrict__ W) {
    __shared__ float As[16][128];
    __shared__ float Bs[16][64];
    const int tid = threadIdx.x;
    const int m0  = blockIdx.x * 128;
    const int tx  = tid & 15;     // N dir: 16 * 4 = 64
    const int ty  = tid >> 4;     // M dir: 16 * 8 = 128

    float acc[8][4];
    #pragma unroll
    for (int i = 0; i < 8; i++)
        #pragma unroll
        for (int j = 0; j < 4; j++) acc[i][j] = 0.f;

    const int ar = tid >> 1;          // 0..127
    const int ac = (tid & 1) * 8;     // 0 or 8
    const int br = tid >> 4;          // 0..15
    const int bc = (tid & 15) * 4;    // 0..60

    for (int k0 = 0; k0 < FIN; k0 += 16) {
        const int gm = m0 + ar;
        float4 a0, a1;
        if (gm < NNODES) {
            const float* xr = x + (size_t)gm * FIN + k0 + ac;
            a0 = *(const float4*)(xr);
            a1 = *(const float4*)(xr + 4);
        } else {
            a0 = make_float4(0.f, 0.f, 0.f, 0.f);
            a1 = a0;
        }
        As[ac + 0][ar] = a0.x; As[ac + 1][ar] = a0.y;
        As[ac + 2][ar] = a0.z; As[ac + 3][ar] = a0.w;
        As[ac + 4][ar] = a1.x; As[ac + 5][ar] = a1.y;
        As[ac + 6][ar] = a1.z; As[ac + 7][ar] = a1.w;
        *(float4*)&Bs[br][bc] = *(const float4*)(W + (size_t)(k0 + br) * 64 + bc);
        __syncthreads();

        #pragma unroll
        for (int k = 0; k < 16; k++) {
            float a[8], b[4];
            float4 av0 = *(const float4*)&As[k][ty * 8];
            float4 av1 = *(const float4*)&As[k][ty * 8 + 4];
            a[0] = av0.x; a[1] = av0.y; a[2] = av0.z; a[3] = av0.w;
            a[4] = av1.x; a[5] = av1.y; a[6] = av1.z; a[7] = av1.w;
            float4 bv = *(const float4*)&Bs[k][tx * 4];
            b[0] = bv.x; b[1] = bv.y; b[2] = bv.z; b[3] = bv.w;
            #pragma unroll
            for (int i = 0; i < 8; i++)
                #pragma unroll
                for (int j = 0; j < 4; j++)
                    acc[i][j] = fmaf(a[i], b[j], acc[i][j]);
        }
        __syncthreads();
    }
    #pragma unroll
    for (int i = 0; i < 8; i++) {
        const int gm = m0 + ty * 8 + i;
        if (gm < NNODES) {
            float4 v = make_float4(acc[i][0], acc[i][1], acc[i][2], acc[i][3]);
            *(float4*)(g_xp1 + (size_t)gm * 64 + tx * 4) = v;
        }
    }
}

// ---------------- 2: per-node attention scores s1[k][n,h] ------------------
__global__ void k_score1(const float* __restrict__ att1) {
    int gid = blockIdx.x * blockDim.x + threadIdx.x;
    if (gid >= NNODES * NH1) return;
    const int n = gid >> 3, h = gid & 7;
    const float4* xr = (const float4*)(g_xp1 + n * F1 + h * 8);
    float4 v0 = xr[0], v1 = xr[1];
    #pragma unroll
    for (int k = 0; k < 3; k++) {
        const float* a = att1 + k * 64 + h * 8;
        float s = v0.x * __ldg(a + 0) + v0.y * __ldg(a + 1)
                + v0.z * __ldg(a + 2) + v0.w * __ldg(a + 3)
                + v1.x * __ldg(a + 4) + v1.y * __ldg(a + 5)
                + v1.z * __ldg(a + 6) + v1.w * __ldg(a + 7);
        g_s1[k][gid] = s;
    }
}

// per-path unnormalized weight (shared by passes A and B; recompute > store:
// keeps a 51MB ee scratch out of L2 so xp1/s1/out1 stay resident)
__device__ __forceinline__ float path_w1(int s, int m, int d, int h) {
    float e = g_s1[0][s * 8 + h] + g_s1[1][m * 8 + h] + g_s1[2][d * 8 + h];
    e = e > 0.f ? e : NEG * e;
    return __expf(e);
}

// ---------------- 3: layer-1 pass A (exp + denom) --------------------------
__global__ void k_passA1() {
    int gid = blockIdx.x * blockDim.x + threadIdx.x;
    if (gid >= NPATH * NH1) return;
    const int p = gid >> 3, h = gid & 7;
    const int s = g_src[p], m = g_mid[p], d = g_dst[p];
    atomicAdd(&g_den1[d * 8 + h], path_w1(s, m, d, h));
}

// ---------------- 4: layer-1 pass B (alpha * xp[src] scatter) --------------
__global__ void k_passB1() {
    int gid = blockIdx.x * blockDim.x + threadIdx.x;
    if (gid >= NPATH * NH1) return;
    const int p = gid >> 3, h = gid & 7;
    const int s = g_src[p], m = g_mid[p], d = g_dst[p];
    const float a = path_w1(s, m, d, h) / g_den1[d * 8 + h];
    const float4* xr = (const float4*)(g_xp1 + s * F1 + h * 8);
    float4 v0 = xr[0], v1 = xr[1];
    float* o = g_out1 + d * F1 + h * 8;
    red_add_v4(o,     a * v0.x, a * v0.y, a * v0.z, a * v0.w);
    red_add_v4(o + 4, a * v1.x, a * v1.y, a * v1.z, a * v1.w);
}

// ---------------- 5: elu(out1+b1) -> xp2 = h@W2, s2 scores -----------------
__global__ void __launch_bounds__(256) k_node2(const float* __restrict__ b1,
                                               const float* __restrict__ W2,
                                               const float* __restrict__ att2) {
    __shared__ float W2s[F1 * NC2];
    __shared__ float b1s[F1];
    __shared__ float att2s[3 * NC2];
    const int tid = threadIdx.x;
    for (int i = tid; i < F1 * NC2; i += blockDim.x) W2s[i] = W2[i];
    if (tid < F1) b1s[tid] = b1[tid];
    if (tid < 3 * NC2) att2s[tid] = att2[tid];
    __syncthreads();
    const int n = blockIdx.x * blockDim.x + tid;
    if (n >= NNODES) return;

    float y[NC2];
    #pragma unroll
    for (int c = 0; c < NC2; c++) y[c] = 0.f;

    const float4* r = (const float4*)(g_out1 + (size_t)n * F1);
    #pragma unroll 4
    for (int j = 0; j < 16; j++) {
        float4 v = r[j];
        float hv[4] = { v.x + b1s[j * 4 + 0], v.y + b1s[j * 4 + 1],
                        v.z + b1s[j * 4 + 2], v.w + b1s[j * 4 + 3] };
        #pragma unroll
        for (int q = 0; q < 4; q++) {
            float hk = hv[q] > 0.f ? hv[q] : expm1f(hv[q]);
            const int k = j * 4 + q;
            #pragma unroll
            for (int c = 0; c < NC2; c++) y[c] = fmaf(hk, W2s[k * NC2 + c], y[c]);
        }
    }
    float s0 = 0.f, s1 = 0.f, s2 = 0.f;
    #pragma unroll
    for (int c = 0; c < NC2; c++) {
        s0 = fmaf(y[c], att2s[c],           s0);
        s1 = fmaf(y[c], att2s[NC2 + c],     s1);
        s2 = fmaf(y[c], att2s[2 * NC2 + c], s2);
    }
    g_s2[0][n] = s0; g_s2[1][n] = s1; g_s2[2][n] = s2;
    float* xp = g_xp2 + n * 8;
    *(float4*)(xp)     = make_float4(y[0], y[1], y[2], y[3]);
    *(float4*)(xp + 4) = make_float4(y[4], y[5], y[6], 0.f);
}

__device__ __forceinline__ float path_w2(int s, int m, int d) {
    float e = g_s2[0][s] + g_s2[1][m] + g_s2[2][d];
    e = e > 0.f ? e : NEG * e;
    return __expf(e);
}

// ---------------- 6: layer-2 pass A ----------------------------------------
__global__ void k_passA2() {
    int p = blockIdx.x * blockDim.x + threadIdx.x;
    if (p >= NPATH) return;
    const int s = g_src[p], m = g_mid[p], d = g_dst[p];
    atomicAdd(&g_den2[d], path_w2(s, m, d));
}

// ---------------- 7: layer-2 pass B ----------------------------------------
__global__ void k_passB2() {
    int p = blockIdx.x * blockDim.x + threadIdx.x;
    if (p >= NPATH) return;
    const int s = g_src[p], m = g_mid[p], d = g_dst[p];
    const float a = path_w2(s, m, d) / g_den2[d];
    const float4* xr = (const float4*)(g_xp2 + s * 8);
    float4 v0 = xr[0], v1 = xr[1];
    float* o = g_logits + d * 8;
    red_add_v4(o,     a * v0.x, a * v0.y, a * v0.z, a * v0.w);
    red_add_v4(o + 4, a * v1.x, a * v1.y, a * v1.z, 0.f);
}

// ---------------- 8: +b2, log_softmax --------------------------------------
__global__ void k_final(const float* __restrict__ b2, float* __restrict__ out) {
    int n = blockIdx.x * blockDim.x + threadIdx.x;
    if (n >= NNODES) return;
    const float4* lr = (const float4*)(g_logits + n * 8);
    float4 l0 = lr[0], l1 = lr[1];
    float v[NC2] = { l0.x + __ldg(b2 + 0), l0.y + __ldg(b2 + 1),
                     l0.z + __ldg(b2 + 2), l0.w + __ldg(b2 + 3),
                     l1.x + __ldg(b2 + 4), l1.y + __ldg(b2 + 5),
                     l1.z + __ldg(b2 + 6) };
    float m = v[0];
    #pragma unroll
    for (int c = 1; c < NC2; c++) m = fmaxf(m, v[c]);
    float ssum = 0.f;
    #pragma unroll
    for (int c = 0; c < NC2; c++) ssum += __expf(v[c] - m);
    float ls = logf(ssum) + m;
    #pragma unroll
    for (int c = 0; c < NC2; c++) out[(size_t)n * NC2 + c] = v[c] - ls;
}

// ---------------- launch ----------------------------------------------------
extern "C" void kernel_launch(void* const* d_in, const int* in_sizes, int n_in,
                              void* d_out, int out_size) {
    const float* x    = (const float*)d_in[0];
    const void*  pi   = d_in[1];                  // int32 or int64: auto-detected
    const float* W1   = (const float*)d_in[2];
    const float* att1 = (const float*)d_in[3];
    const float* b1   = (const float*)d_in[4];
    const float* W2   = (const float*)d_in[5];
    const float* att2 = (const float*)d_in[6];
    const float* b2   = (const float*)d_in[7];
    float*       out  = (float*)d_out;

    k_detect<<<1, 1024>>>((const unsigned long long*)pi);
    k_convert<<<(NPATH + 255) / 256, 256>>>(pi);
    k_zero<<<(NNODES * F1 / 4 + 255) / 256, 256>>>();
    k_gemm1<<<(NNODES + 127) / 128, 256>>>(x, W1);
    k_score1<<<(NNODES * NH1 + 255) / 256, 256>>>(att1);
    k_passA1<<<(NPATH * NH1 + 255) / 256, 256>>>();
    k_passB1<<<(NPATH * NH1 + 255) / 256, 256>>>();
    k_node2<<<(NNODES + 255) / 256, 256>>>(b1, W2, att2);
    k_passA2<<<(NPATH + 255) / 256, 256>>>();
    k_passB2<<<(NPATH + 255) / 256, 256>>>();
    k_final<<<(NNODES + 255) / 256, 256>>>(b2, out);
}

// round 8
// speedup vs baseline: 1.2059x; 1.2059x over previous
#include <cuda_runtime.h>
#include <cuda_bf16.h>
#include <cstdint>
#include <math.h>

#define NNODES 100000
#define FIN    512
#define NPATH  1600000
#define NH1    8
#define F1     64      // H1*C1
#define NC2    7
#define NEG    0.2f

// ---------------- scratch (device globals; no allocations) ----------------
static __device__ float g_xp1[NNODES * F1];          // 25.6 MB
static __device__ float g_s1[3][NNODES * NH1];       //  9.6 MB
static __device__ float g_den1[NNODES * NH1];        //  3.2 MB
static __device__ float g_out1[NNODES * F1];         // 25.6 MB
static __device__ float g_xp2[NNODES * 8];           //  3.2 MB
static __device__ float g_s2[3][NNODES];             //  1.2 MB
static __device__ float g_den2[NNODES];              //  0.4 MB
static __device__ float g_logits[NNODES * 8];        //  3.2 MB
static __device__ int   g_src[NPATH], g_mid[NPATH], g_dst[NPATH];  // 19.2 MB
static __device__ int   g_is64;
// W1 pre-split hi/lo bf16, transposed to [n][k] for the TC GEMM
static __device__ __nv_bfloat16 g_Wt_hi[F1 * FIN];   // 64 KB
static __device__ __nv_bfloat16 g_Wt_lo[F1 * FIN];   // 64 KB

__device__ __forceinline__ void red_add_v4(float* p, float a, float b, float c, float d) {
    asm volatile("red.global.add.v4.f32 [%0], {%1,%2,%3,%4};"
                 :: "l"(p), "f"(a), "f"(b), "f"(c), "f"(d) : "memory");
}

__device__ __forceinline__ void mma_bf16(float& d0, float& d1, float& d2, float& d3,
                                         unsigned a0, unsigned a1, unsigned a2, unsigned a3,
                                         unsigned b0, unsigned b1) {
    asm volatile("mma.sync.aligned.m16n8k16.row.col.f32.bf16.bf16.f32 "
                 "{%0,%1,%2,%3}, {%4,%5,%6,%7}, {%8,%9}, {%0,%1,%2,%3};"
                 : "+f"(d0), "+f"(d1), "+f"(d2), "+f"(d3)
                 : "r"(a0), "r"(a1), "r"(a2), "r"(a3), "r"(b0), "r"(b1));
}

// ---------------- 0a: detect path_index dtype -------------------------------
__global__ void k_detect(const unsigned long long* __restrict__ pi) {
    __shared__ int bad;
    if (threadIdx.x == 0) bad = 0;
    __syncthreads();
    unsigned long long v = pi[threadIdx.x];
    if (v >= (unsigned long long)NNODES) atomicOr(&bad, 1);
    __syncthreads();
    if (threadIdx.x == 0) g_is64 = bad ? 0 : 1;
}

__device__ __forceinline__ int clamp_idx(long long v) {
    int i = (int)v;
    i = i < 0 ? 0 : i;
    return i >= NNODES ? NNODES - 1 : i;
}

// ---------------- 0b: convert path indices to int32 SoA ---------------------
__global__ void k_convert(const void* __restrict__ piv) {
    int i = blockIdx.x * blockDim.x + threadIdx.x;
    if (i >= NPATH) return;
    long long s, m, d;
    if (g_is64) {
        const long long* pi = (const long long*)piv;
        s = pi[i]; m = pi[NPATH + i]; d = pi[2 * NPATH + i];
    } else {
        const int* pi = (const int*)piv;
        s = pi[i]; m = pi[NPATH + i]; d = pi[2 * NPATH + i];
    }
    g_src[i] = clamp_idx(s);
    g_mid[i] = clamp_idx(m);
    g_dst[i] = clamp_idx(d);
}

// ---------------- 0c: zero accumulators (every replay!) ---------------------
__global__ void k_zero() {
    int i = blockIdx.x * blockDim.x + threadIdx.x;
    if (i < NNODES * F1 / 4)  ((float4*)g_out1)[i]   = make_float4(0.f, 0.f, 0.f, 0.f);
    if (i < NNODES * NH1 / 4) ((float4*)g_den1)[i]   = make_float4(0.f, 0.f, 0.f, 0.f);
    if (i < NNODES * 8 / 4)   ((float4*)g_logits)[i] = make_float4(0.f, 0.f, 0.f, 0.f);
    if (i < NNODES / 4)       ((float4*)g_den2)[i]   = make_float4(0.f, 0.f, 0.f, 0.f);
}

// ---------------- 0d: split W1 into bf16 hi/lo, transposed [n][k] -----------
__global__ void k_splitW(const float* __restrict__ W) {
    int i = blockIdx.x * blockDim.x + threadIdx.x;   // i = k*64+n
    if (i >= FIN * F1) return;
    int k = i >> 6, n = i & 63;
    float w = W[i];
    __nv_bfloat16 hi = __float2bfloat16(w);
    __nv_bfloat16 lo = __float2bfloat16(w - __bfloat162float(hi));
    g_Wt_hi[n * FIN + k] = hi;
    g_Wt_lo[n * FIN + k] = lo;
}

// ---------------- 1: xp1 = x @ W1  (bf16 tensor-core, 3-term split) --------
// BM=128, BN=64, BK=32. 256 threads = 8 warps (4 M x 2 N), warp tile 32x32.
// Smem pitch 40 bf16 -> conflict-free fragment LDS.
#define PA 40
__global__ void __launch_bounds__(256) k_gemm1(const float* __restrict__ x) {
    __shared__ __nv_bfloat16 Ahi[128 * PA];
    __shared__ __nv_bfloat16 Alo[128 * PA];
    __shared__ __nv_bfloat16 Bhi[64 * PA];
    __shared__ __nv_bfloat16 Blo[64 * PA];

    const int tid   = threadIdx.x;
    const int lane  = tid & 31;
    const int warp  = tid >> 5;
    const int warpM = warp >> 1;          // 0..3
    const int warpN = warp & 1;           // 0..1
    const int qr    = lane >> 2;          // 0..7
    const int qc    = lane & 3;           // 0..3
    const int m0    = blockIdx.x * 128;

    float acc[2][4][4];
    #pragma unroll
    for (int mt = 0; mt < 2; mt++)
        #pragma unroll
        for (int nt = 0; nt < 4; nt++)
            #pragma unroll
            for (int r = 0; r < 4; r++) acc[mt][nt][r] = 0.f;

    // A loader: thread t -> row t>>1, k-segment (t&1)*16
    const int am    = tid >> 1;
    const int akseg = (tid & 1) * 16;
    const int gm    = m0 + am;
    const bool mok  = gm < NNODES;
    const float* xrow = x + (size_t)gm * FIN;
    // B loader: thread t -> n = t>>2, k-offset (t&3)*8
    const int bn    = tid >> 2;
    const int bkoff = (tid & 3) * 8;

    for (int k0 = 0; k0 < FIN; k0 += 32) {
        // ---- load + split A tile ----
        float av[16];
        if (mok) {
            #pragma unroll
            for (int j = 0; j < 4; j++) {
                float4 v = *(const float4*)(xrow + k0 + akseg + j * 4);
                av[j * 4 + 0] = v.x; av[j * 4 + 1] = v.y;
                av[j * 4 + 2] = v.z; av[j * 4 + 3] = v.w;
            }
        } else {
            #pragma unroll
            for (int j = 0; j < 16; j++) av[j] = 0.f;
        }
        #pragma unroll
        for (int j = 0; j < 16; j += 2) {
            __nv_bfloat16 h0 = __float2bfloat16(av[j]);
            __nv_bfloat16 h1 = __float2bfloat16(av[j + 1]);
            __nv_bfloat16 l0 = __float2bfloat16(av[j]     - __bfloat162float(h0));
            __nv_bfloat16 l1 = __float2bfloat16(av[j + 1] - __bfloat162float(h1));
            __nv_bfloat162 hp; hp.x = h0; hp.y = h1;
            __nv_bfloat162 lp; lp.x = l0; lp.y = l1;
            *(__nv_bfloat162*)&Ahi[am * PA + akseg + j] = hp;
            *(__nv_bfloat162*)&Alo[am * PA + akseg + j] = lp;
        }
        // ---- load B tile (already bf16, transposed [n][k]) ----
        {
            uint4 vh = *(const uint4*)&g_Wt_hi[bn * FIN + k0 + bkoff];
            uint4 vl = *(const uint4*)&g_Wt_lo[bn * FIN + k0 + bkoff];
            *(uint4*)&Bhi[bn * PA + bkoff] = vh;
            *(uint4*)&Blo[bn * PA + bkoff] = vl;
        }
        __syncthreads();

        #pragma unroll
        for (int kk = 0; kk < 32; kk += 16) {
            unsigned ah[2][4], al[2][4];
            #pragma unroll
            for (int mt = 0; mt < 2; mt++) {
                int r = warpM * 32 + mt * 16 + qr;
                int c = kk + qc * 2;
                ah[mt][0] = *(const unsigned*)&Ahi[(r)     * PA + c];
                ah[mt][1] = *(const unsigned*)&Ahi[(r + 8) * PA + c];
                ah[mt][2] = *(const unsigned*)&Ahi[(r)     * PA + c + 8];
                ah[mt][3] = *(const unsigned*)&Ahi[(r + 8) * PA + c + 8];
                al[mt][0] = *(const unsigned*)&Alo[(r)     * PA + c];
                al[mt][1] = *(const unsigned*)&Alo[(r + 8) * PA + c];
                al[mt][2] = *(const unsigned*)&Alo[(r)     * PA + c + 8];
                al[mt][3] = *(const unsigned*)&Alo[(r + 8) * PA + c + 8];
            }
            unsigned bh[4][2], bl[4][2];
            #pragma unroll
            for (int nt = 0; nt < 4; nt++) {
                int n = warpN * 32 + nt * 8 + qr;
                int c = kk + qc * 2;
                bh[nt][0] = *(const unsigned*)&Bhi[n * PA + c];
                bh[nt][1] = *(const unsigned*)&Bhi[n * PA + c + 8];
                bl[nt][0] = *(const unsigned*)&Blo[n * PA + c];
                bl[nt][1] = *(const unsigned*)&Blo[n * PA + c + 8];
            }
            #pragma unroll
            for (int mt = 0; mt < 2; mt++)
                #pragma unroll
                for (int nt = 0; nt < 4; nt++) {
                    float* d = acc[mt][nt];
                    mma_bf16(d[0], d[1], d[2], d[3],
                             ah[mt][0], ah[mt][1], ah[mt][2], ah[mt][3],
                             bh[nt][0], bh[nt][1]);
                    mma_bf16(d[0], d[1], d[2], d[3],
                             al[mt][0], al[mt][1], al[mt][2], al[mt][3],
                             bh[nt][0], bh[nt][1]);
                    mma_bf16(d[0], d[1], d[2], d[3],
                             ah[mt][0], ah[mt][1], ah[mt][2], ah[mt][3],
                             bl[nt][0], bl[nt][1]);
                }
        }
        __syncthreads();
    }
    // ---- epilogue: acc -> g_xp1 ----
    #pragma unroll
    for (int mt = 0; mt < 2; mt++) {
        int r = m0 + warpM * 32 + mt * 16 + qr;
        #pragma unroll
        for (int nt = 0; nt < 4; nt++) {
            int c = warpN * 32 + nt * 8 + qc * 2;
            if (r < NNODES)
                *(float2*)(g_xp1 + (size_t)r * 64 + c) =
                    make_float2(acc[mt][nt][0], acc[mt][nt][1]);
            if (r + 8 < NNODES)
                *(float2*)(g_xp1 + (size_t)(r + 8) * 64 + c) =
                    make_float2(acc[mt][nt][2], acc[mt][nt][3]);
        }
    }
}

// ---------------- 2: per-node attention scores s1[k][n,h] ------------------
__global__ void k_score1(const float* __restrict__ att1) {
    int gid = blockIdx.x * blockDim.x + threadIdx.x;
    if (gid >= NNODES * NH1) return;
    const int n = gid >> 3, h = gid & 7;
    const float4* xr = (const float4*)(g_xp1 + n * F1 + h * 8);
    float4 v0 = xr[0], v1 = xr[1];
    #pragma unroll
    for (int k = 0; k < 3; k++) {
        const float* a = att1 + k * 64 + h * 8;
        float s = v0.x * __ldg(a + 0) + v0.y * __ldg(a + 1)
                + v0.z * __ldg(a + 2) + v0.w * __ldg(a + 3)
                + v1.x * __ldg(a + 4) + v1.y * __ldg(a + 5)
                + v1.z * __ldg(a + 6) + v1.w * __ldg(a + 7);
        g_s1[k][gid] = s;
    }
}

__device__ __forceinline__ float path_w1(int s, int m, int d, int h) {
    float e = g_s1[0][s * 8 + h] + g_s1[1][m * 8 + h] + g_s1[2][d * 8 + h];
    e = e > 0.f ? e : NEG * e;
    return __expf(e);
}

// ---------------- 3: layer-1 pass A (2 threads/path, vector RED) -----------
__global__ void k_passA1() {
    int gid = blockIdx.x * blockDim.x + threadIdx.x;
    if (gid >= NPATH * 2) return;
    const int p = gid >> 1, q = (gid & 1) * 4;
    const int s = g_src[p], m = g_mid[p], d = g_dst[p];
    float4 e0 = *(const float4*)&g_s1[0][s * 8 + q];
    float4 e1 = *(const float4*)&g_s1[1][m * 8 + q];
    float4 e2 = *(const float4*)&g_s1[2][d * 8 + q];
    float ex = e0.x + e1.x + e2.x, ey = e0.y + e1.y + e2.y;
    float ez = e0.z + e1.z + e2.z, ew = e0.w + e1.w + e2.w;
    ex = ex > 0.f ? ex : NEG * ex;  ey = ey > 0.f ? ey : NEG * ey;
    ez = ez > 0.f ? ez : NEG * ez;  ew = ew > 0.f ? ew : NEG * ew;
    red_add_v4(&g_den1[d * 8 + q], __expf(ex), __expf(ey), __expf(ez), __expf(ew));
}

// ---------------- 4: layer-1 pass B (alpha * xp[src] scatter) --------------
__global__ void k_passB1() {
    int gid = blockIdx.x * blockDim.x + threadIdx.x;
    if (gid >= NPATH * NH1) return;
    const int p = gid >> 3, h = gid & 7;
    const int s = g_src[p], m = g_mid[p], d = g_dst[p];
    const float a = path_w1(s, m, d, h) / g_den1[d * 8 + h];
    const float4* xr = (const float4*)(g_xp1 + s * F1 + h * 8);
    float4 v0 = xr[0], v1 = xr[1];
    float* o = g_out1 + d * F1 + h * 8;
    red_add_v4(o,     a * v0.x, a * v0.y, a * v0.z, a * v0.w);
    red_add_v4(o + 4, a * v1.x, a * v1.y, a * v1.z, a * v1.w);
}

// ---------------- 5: elu(out1+b1) -> xp2 = h@W2, s2 scores -----------------
__global__ void __launch_bounds__(256) k_node2(const float* __restrict__ b1,
                                               const float* __restrict__ W2,
                                               const float* __restrict__ att2) {
    __shared__ float W2s[F1 * NC2];
    __shared__ float b1s[F1];
    __shared__ float att2s[3 * NC2];
    const int tid = threadIdx.x;
    for (int i = tid; i < F1 * NC2; i += blockDim.x) W2s[i] = W2[i];
    if (tid < F1) b1s[tid] = b1[tid];
    if (tid < 3 * NC2) att2s[tid] = att2[tid];
    __syncthreads();
    const int n = blockIdx.x * blockDim.x + tid;
    if (n >= NNODES) return;

    float y[NC2];
    #pragma unroll
    for (int c = 0; c < NC2; c++) y[c] = 0.f;

    const float4* r = (const float4*)(g_out1 + (size_t)n * F1);
    #pragma unroll 4
    for (int j = 0; j < 16; j++) {
        float4 v = r[j];
        float hv[4] = { v.x + b1s[j * 4 + 0], v.y + b1s[j * 4 + 1],
                        v.z + b1s[j * 4 + 2], v.w + b1s[j * 4 + 3] };
        #pragma unroll
        for (int q = 0; q < 4; q++) {
            float hk = hv[q] > 0.f ? hv[q] : expm1f(hv[q]);
            const int k = j * 4 + q;
            #pragma unroll
            for (int c = 0; c < NC2; c++) y[c] = fmaf(hk, W2s[k * NC2 + c], y[c]);
        }
    }
    float s0 = 0.f, s1 = 0.f, s2 = 0.f;
    #pragma unroll
    for (int c = 0; c < NC2; c++) {
        s0 = fmaf(y[c], att2s[c],           s0);
        s1 = fmaf(y[c], att2s[NC2 + c],     s1);
        s2 = fmaf(y[c], att2s[2 * NC2 + c], s2);
    }
    g_s2[0][n] = s0; g_s2[1][n] = s1; g_s2[2][n] = s2;
    float* xp = g_xp2 + n * 8;
    *(float4*)(xp)     = make_float4(y[0], y[1], y[2], y[3]);
    *(float4*)(xp + 4) = make_float4(y[4], y[5], y[6], 0.f);
}

__device__ __forceinline__ float path_w2(int s, int m, int d) {
    float e = g_s2[0][s] + g_s2[1][m] + g_s2[2][d];
    e = e > 0.f ? e : NEG * e;
    return __expf(e);
}

// ---------------- 6: layer-2 pass A ----------------------------------------
__global__ void k_passA2() {
    int p = blockIdx.x * blockDim.x + threadIdx.x;
    if (p >= NPATH) return;
    const int s = g_src[p], m = g_mid[p], d = g_dst[p];
    atomicAdd(&g_den2[d], path_w2(s, m, d));
}

// ---------------- 7: layer-2 pass B ----------------------------------------
__global__ void k_passB2() {
    int p = blockIdx.x * blockDim.x + threadIdx.x;
    if (p >= NPATH) return;
    const int s = g_src[p], m = g_mid[p], d = g_dst[p];
    const float a = path_w2(s, m, d) / g_den2[d];
    const float4* xr = (const float4*)(g_xp2 + s * 8);
    float4 v0 = xr[0], v1 = xr[1];
    float* o = g_logits + d * 8;
    red_add_v4(o,     a * v0.x, a * v0.y, a * v0.z, a * v0.w);
    red_add_v4(o + 4, a * v1.x, a * v1.y, a * v1.z, 0.f);
}

// ---------------- 8: +b2, log_softmax --------------------------------------
__global__ void k_final(const float* __restrict__ b2, float* __restrict__ out) {
    int n = blockIdx.x * blockDim.x + threadIdx.x;
    if (n >= NNODES) return;
    const float4* lr = (const float4*)(g_logits + n * 8);
    float4 l0 = lr[0], l1 = lr[1];
    float v[NC2] = { l0.x + __ldg(b2 + 0), l0.y + __ldg(b2 + 1),
                     l0.z + __ldg(b2 + 2), l0.w + __ldg(b2 + 3),
                     l1.x + __ldg(b2 + 4), l1.y + __ldg(b2 + 5),
                     l1.z + __ldg(b2 + 6) };
    float m = v[0];
    #pragma unroll
    for (int c = 1; c < NC2; c++) m = fmaxf(m, v[c]);
    float ssum = 0.f;
    #pragma unroll
    for (int c = 0; c < NC2; c++) ssum += __expf(v[c] - m);
    float ls = logf(ssum) + m;
    #pragma unroll
    for (int c = 0; c < NC2; c++) out[(size_t)n * NC2 + c] = v[c] - ls;
}

// ---------------- launch ----------------------------------------------------
extern "C" void kernel_launch(void* const* d_in, const int* in_sizes, int n_in,
                              void* d_out, int out_size) {
    const float* x    = (const float*)d_in[0];
    const void*  pi   = d_in[1];
    const float* W1   = (const float*)d_in[2];
    const float* att1 = (const float*)d_in[3];
    const float* b1   = (const float*)d_in[4];
    const float* W2   = (const float*)d_in[5];
    const float* att2 = (const float*)d_in[6];
    const float* b2   = (const float*)d_in[7];
    float*       out  = (float*)d_out;

    k_detect<<<1, 1024>>>((const unsigned long long*)pi);
    k_convert<<<(NPATH + 255) / 256, 256>>>(pi);
    k_zero<<<(NNODES * F1 / 4 + 255) / 256, 256>>>();
    k_splitW<<<(FIN * F1 + 255) / 256, 256>>>(W1);
    k_gemm1<<<(NNODES + 127) / 128, 256>>>(x);
    k_score1<<<(NNODES * NH1 + 255) / 256, 256>>>(att1);
    k_passA1<<<(NPATH * 2 + 255) / 256, 256>>>();
    k_passB1<<<(NPATH * NH1 + 255) / 256, 256>>>();
    k_node2<<<(NNODES + 255) / 256, 256>>>(b1, W2, att2);
    k_passA2<<<(NPATH + 255) / 256, 256>>>();
    k_passB2<<<(NPATH + 255) / 256, 256>>>();
    k_final<<<(NNODES + 255) / 256, 256>>>(b2, out);
}

// round 11
// speedup vs baseline: 1.3857x; 1.1491x over previous
#include <cuda_runtime.h>
#include <cuda_bf16.h>
#include <cstdint>
#include <math.h>

#define NNODES 100000
#define FIN    512
#define NPATH  1600000
#define NH1    8
#define F1     64      // H1*C1
#define NC2    7
#define NEG    0.2f

// ---------------- scratch (device globals; no allocations) ----------------
static __device__ float g_xp1[NNODES * F1];          // 25.6 MB
static __device__ float g_s1[3][NNODES * NH1];       //  9.6 MB
static __device__ float g_den1[NNODES * NH1];        //  3.2 MB
static __device__ float g_out1[NNODES * F1];         // 25.6 MB (UNNORMALIZED numerator)
static __device__ float g_xp2[NNODES * 8];           //  3.2 MB
static __device__ float g_s2[3][NNODES];             //  1.2 MB
static __device__ float g_den2[NNODES];              //  0.4 MB
static __device__ float g_logits[NNODES * 8];        //  3.2 MB (UNNORMALIZED)
static __device__ int   g_src[NPATH], g_mid[NPATH], g_dst[NPATH];  // 19.2 MB
static __device__ int   g_is64;
// W1 pre-split hi/lo bf16, transposed to [n][k] for the TC GEMM
static __device__ __nv_bfloat16 g_Wt_hi[F1 * FIN];   // 64 KB
static __device__ __nv_bfloat16 g_Wt_lo[F1 * FIN];   // 64 KB

__device__ __forceinline__ void red_add_v4(float* p, float a, float b, float c, float d) {
    asm volatile("red.global.add.v4.f32 [%0], {%1,%2,%3,%4};"
                 :: "l"(p), "f"(a), "f"(b), "f"(c), "f"(d) : "memory");
}

__device__ __forceinline__ void mma_bf16(float& d0, float& d1, float& d2, float& d3,
                                         unsigned a0, unsigned a1, unsigned a2, unsigned a3,
                                         unsigned b0, unsigned b1) {
    asm volatile("mma.sync.aligned.m16n8k16.row.col.f32.bf16.bf16.f32 "
                 "{%0,%1,%2,%3}, {%4,%5,%6,%7}, {%8,%9}, {%0,%1,%2,%3};"
                 : "+f"(d0), "+f"(d1), "+f"(d2), "+f"(d3)
                 : "r"(a0), "r"(a1), "r"(a2), "r"(a3), "r"(b0), "r"(b1));
}

// ---------------- 0a: detect path_index dtype -------------------------------
__global__ void k_detect(const unsigned long long* __restrict__ pi) {
    __shared__ int bad;
    if (threadIdx.x == 0) bad = 0;
    __syncthreads();
    unsigned long long v = pi[threadIdx.x];
    if (v >= (unsigned long long)NNODES) atomicOr(&bad, 1);
    __syncthreads();
    if (threadIdx.x == 0) g_is64 = bad ? 0 : 1;
}

__device__ __forceinline__ int clamp_idx(long long v) {
    int i = (int)v;
    i = i < 0 ? 0 : i;
    return i >= NNODES ? NNODES - 1 : i;
}

// ---------------- 0b: convert indices + zero accumulators (one kernel) ------
__global__ void k_prep(const void* __restrict__ piv) {
    int i = blockIdx.x * blockDim.x + threadIdx.x;
    if (i < NPATH) {
        long long s, m, d;
        if (g_is64) {
            const long long* pi = (const long long*)piv;
            s = pi[i]; m = pi[NPATH + i]; d = pi[2 * NPATH + i];
        } else {
            const int* pi = (const int*)piv;
            s = pi[i]; m = pi[NPATH + i]; d = pi[2 * NPATH + i];
        }
        g_src[i] = clamp_idx(s);
        g_mid[i] = clamp_idx(m);
        g_dst[i] = clamp_idx(d);
    }
    const float4 z = make_float4(0.f, 0.f, 0.f, 0.f);
    if (i < NNODES * F1 / 4)  ((float4*)g_out1)[i]   = z;
    if (i < NNODES * NH1 / 4) ((float4*)g_den1)[i]   = z;
    if (i < NNODES * 8 / 4)   ((float4*)g_logits)[i] = z;
    if (i < NNODES / 4)       ((float4*)g_den2)[i]   = z;
}

// ---------------- 0c: split W1 into bf16 hi/lo, transposed [n][k] -----------
__global__ void k_splitW(const float* __restrict__ W) {
    int i = blockIdx.x * blockDim.x + threadIdx.x;   // i = k*64+n
    if (i >= FIN * F1) return;
    int k = i >> 6, n = i & 63;
    float w = W[i];
    __nv_bfloat16 hi = __float2bfloat16(w);
    __nv_bfloat16 lo = __float2bfloat16(w - __bfloat162float(hi));
    g_Wt_hi[n * FIN + k] = hi;
    g_Wt_lo[n * FIN + k] = lo;
}

// ---------------- 1: xp1 = x @ W1  (bf16 tensor-core, 3-term split) --------
#define PA 40
__global__ void __launch_bounds__(256) k_gemm1(const float* __restrict__ x) {
    __shared__ __nv_bfloat16 Ahi[128 * PA];
    __shared__ __nv_bfloat16 Alo[128 * PA];
    __shared__ __nv_bfloat16 Bhi[64 * PA];
    __shared__ __nv_bfloat16 Blo[64 * PA];

    const int tid   = threadIdx.x;
    const int lane  = tid & 31;
    const int warp  = tid >> 5;
    const int warpM = warp >> 1;
    const int warpN = warp & 1;
    const int qr    = lane >> 2;
    const int qc    = lane & 3;
    const int m0    = blockIdx.x * 128;

    float acc[2][4][4];
    #pragma unroll
    for (int mt = 0; mt < 2; mt++)
        #pragma unroll
        for (int nt = 0; nt < 4; nt++)
            #pragma unroll
            for (int r = 0; r < 4; r++) acc[mt][nt][r] = 0.f;

    const int am    = tid >> 1;
    const int akseg = (tid & 1) * 16;
    const int gm    = m0 + am;
    const bool mok  = gm < NNODES;
    const float* xrow = x + (size_t)gm * FIN;
    const int bn    = tid >> 2;
    const int bkoff = (tid & 3) * 8;

    for (int k0 = 0; k0 < FIN; k0 += 32) {
        float av[16];
        if (mok) {
            #pragma unroll
            for (int j = 0; j < 4; j++) {
                float4 v = *(const float4*)(xrow + k0 + akseg + j * 4);
                av[j * 4 + 0] = v.x; av[j * 4 + 1] = v.y;
                av[j * 4 + 2] = v.z; av[j * 4 + 3] = v.w;
            }
        } else {
            #pragma unroll
            for (int j = 0; j < 16; j++) av[j] = 0.f;
        }
        #pragma unroll
        for (int j = 0; j < 16; j += 2) {
            __nv_bfloat16 h0 = __float2bfloat16(av[j]);
            __nv_bfloat16 h1 = __float2bfloat16(av[j + 1]);
            __nv_bfloat16 l0 = __float2bfloat16(av[j]     - __bfloat162float(h0));
            __nv_bfloat16 l1 = __float2bfloat16(av[j + 1] - __bfloat162float(h1));
            __nv_bfloat162 hp; hp.x = h0; hp.y = h1;
            __nv_bfloat162 lp; lp.x = l0; lp.y = l1;
            *(__nv_bfloat162*)&Ahi[am * PA + akseg + j] = hp;
            *(__nv_bfloat162*)&Alo[am * PA + akseg + j] = lp;
        }
        {
            uint4 vh = *(const uint4*)&g_Wt_hi[bn * FIN + k0 + bkoff];
            uint4 vl = *(const uint4*)&g_Wt_lo[bn * FIN + k0 + bkoff];
            *(uint4*)&Bhi[bn * PA + bkoff] = vh;
            *(uint4*)&Blo[bn * PA + bkoff] = vl;
        }
        __syncthreads();

        #pragma unroll
        for (int kk = 0; kk < 32; kk += 16) {
            unsigned ah[2][4], al[2][4];
            #pragma unroll
            for (int mt = 0; mt < 2; mt++) {
                int r = warpM * 32 + mt * 16 + qr;
                int c = kk + qc * 2;
                ah[mt][0] = *(const unsigned*)&Ahi[(r)     * PA + c];
                ah[mt][1] = *(const unsigned*)&Ahi[(r + 8) * PA + c];
                ah[mt][2] = *(const unsigned*)&Ahi[(r)     * PA + c + 8];
                ah[mt][3] = *(const unsigned*)&Ahi[(r + 8) * PA + c + 8];
                al[mt][0] = *(const unsigned*)&Alo[(r)     * PA + c];
                al[mt][1] = *(const unsigned*)&Alo[(r + 8) * PA + c];
                al[mt][2] = *(const unsigned*)&Alo[(r)     * PA + c + 8];
                al[mt][3] = *(const unsigned*)&Alo[(r + 8) * PA + c + 8];
            }
            unsigned bh[4][2], bl[4][2];
            #pragma unroll
            for (int nt = 0; nt < 4; nt++) {
                int n = warpN * 32 + nt * 8 + qr;
                int c = kk + qc * 2;
                bh[nt][0] = *(const unsigned*)&Bhi[n * PA + c];
                bh[nt][1] = *(const unsigned*)&Bhi[n * PA + c + 8];
                bl[nt][0] = *(const unsigned*)&Blo[n * PA + c];
                bl[nt][1] = *(const unsigned*)&Blo[n * PA + c + 8];
            }
            #pragma unroll
            for (int mt = 0; mt < 2; mt++)
                #pragma unroll
                for (int nt = 0; nt < 4; nt++) {
                    float* d = acc[mt][nt];
                    mma_bf16(d[0], d[1], d[2], d[3],
                             ah[mt][0], ah[mt][1], ah[mt][2], ah[mt][3],
                             bh[nt][0], bh[nt][1]);
                    mma_bf16(d[0], d[1], d[2], d[3],
                             al[mt][0], al[mt][1], al[mt][2], al[mt][3],
                             bh[nt][0], bh[nt][1]);
                    mma_bf16(d[0], d[1], d[2], d[3],
                             ah[mt][0], ah[mt][1], ah[mt][2], ah[mt][3],
                             bl[nt][0], bl[nt][1]);
                }
        }
        __syncthreads();
    }
    #pragma unroll
    for (int mt = 0; mt < 2; mt++) {
        int r = m0 + warpM * 32 + mt * 16 + qr;
        #pragma unroll
        for (int nt = 0; nt < 4; nt++) {
            int c = warpN * 32 + nt * 8 + qc * 2;
            if (r < NNODES)
                *(float2*)(g_xp1 + (size_t)r * 64 + c) =
                    make_float2(acc[mt][nt][0], acc[mt][nt][1]);
            if (r + 8 < NNODES)
                *(float2*)(g_xp1 + (size_t)(r + 8) * 64 + c) =
                    make_float2(acc[mt][nt][2], acc[mt][nt][3]);
        }
    }
}

// ---------------- 2: per-node attention scores s1[k][n,h] ------------------
__global__ void k_score1(const float* __restrict__ att1) {
    int gid = blockIdx.x * blockDim.x + threadIdx.x;
    if (gid >= NNODES * NH1) return;
    const int n = gid >> 3, h = gid & 7;
    const float4* xr = (const float4*)(g_xp1 + n * F1 + h * 8);
    float4 v0 = xr[0], v1 = xr[1];
    #pragma unroll
    for (int k = 0; k < 3; k++) {
        const float* a = att1 + k * 64 + h * 8;
        float s = v0.x * __ldg(a + 0) + v0.y * __ldg(a + 1)
                + v0.z * __ldg(a + 2) + v0.w * __ldg(a + 3)
                + v1.x * __ldg(a + 4) + v1.y * __ldg(a + 5)
                + v1.z * __ldg(a + 6) + v1.w * __ldg(a + 7);
        g_s1[k][gid] = s;
    }
}

// ---------------- 3: FUSED layer-1: w = exp(lrelu(e)); scatter w and w*x ----
// 8 threads per path (one per head), all in the same warp. Softmax division
// is factored out: numerator and denominator accumulate unnormalized; node2
// divides. Saves the entire separate denominator pass.
__global__ void k_fused1() {
    int gid = blockIdx.x * blockDim.x + threadIdx.x;
    if (gid >= NPATH * NH1) return;
    const int p = gid >> 3, h = gid & 7;
    const int s = g_src[p], m = g_mid[p], d = g_dst[p];
    float e = g_s1[0][s * 8 + h] + g_s1[1][m * 8 + h] + g_s1[2][d * 8 + h];
    e = e > 0.f ? e : NEG * e;
    const float w = __expf(e);
    // assemble per-path den v4 on lanes h%4==0 via shuffles (path = 8 lanes)
    const unsigned FULL = 0xFFFFFFFFu;
    float w1 = __shfl_down_sync(FULL, w, 1);
    float w2 = __shfl_down_sync(FULL, w, 2);
    float w3 = __shfl_down_sync(FULL, w, 3);
    if ((h & 3) == 0) red_add_v4(&g_den1[d * 8 + h], w, w1, w2, w3);
    // numerator scatter
    const float4* xr = (const float4*)(g_xp1 + s * F1 + h * 8);
    float4 v0 = xr[0], v1 = xr[1];
    float* o = g_out1 + d * F1 + h * 8;
    red_add_v4(o,     w * v0.x, w * v0.y, w * v0.z, w * v0.w);
    red_add_v4(o + 4, w * v1.x, w * v1.y, w * v1.z, w * v1.w);
}

// ---------------- 4: normalize, elu(+b1) -> xp2 = h@W2, s2 scores -----------
__global__ void __launch_bounds__(256) k_node2(const float* __restrict__ b1,
                                               const float* __restrict__ W2,
                                               const float* __restrict__ att2) {
    __shared__ float W2s[F1 * NC2];
    __shared__ float b1s[F1];
    __shared__ float att2s[3 * NC2];
    const int tid = threadIdx.x;
    for (int i = tid; i < F1 * NC2; i += blockDim.x) W2s[i] = W2[i];
    if (tid < F1) b1s[tid] = b1[tid];
    if (tid < 3 * NC2) att2s[tid] = att2[tid];
    __syncthreads();
    const int n = blockIdx.x * blockDim.x + tid;
    if (n >= NNODES) return;

    float dinv[NH1];
    {
        const float4* dr = (const float4*)(g_den1 + n * NH1);
        float4 d0 = dr[0], d1 = dr[1];
        dinv[0] = 1.f / (d0.x + 1e-16f); dinv[1] = 1.f / (d0.y + 1e-16f);
        dinv[2] = 1.f / (d0.z + 1e-16f); dinv[3] = 1.f / (d0.w + 1e-16f);
        dinv[4] = 1.f / (d1.x + 1e-16f); dinv[5] = 1.f / (d1.y + 1e-16f);
        dinv[6] = 1.f / (d1.z + 1e-16f); dinv[7] = 1.f / (d1.w + 1e-16f);
    }

    float y[NC2];
    #pragma unroll
    for (int c = 0; c < NC2; c++) y[c] = 0.f;

    const float4* r = (const float4*)(g_out1 + (size_t)n * F1);
    #pragma unroll 4
    for (int j = 0; j < 16; j++) {
        float4 v = r[j];
        const float di = dinv[j >> 1];          // channels j*4..j*4+3 share head j/2
        float hv[4] = { v.x * di + b1s[j * 4 + 0], v.y * di + b1s[j * 4 + 1],
                        v.z * di + b1s[j * 4 + 2], v.w * di + b1s[j * 4 + 3] };
        #pragma unroll
        for (int q = 0; q < 4; q++) {
            float hk = hv[q] > 0.f ? hv[q] : expm1f(hv[q]);
            const int k = j * 4 + q;
            #pragma unroll
            for (int c = 0; c < NC2; c++) y[c] = fmaf(hk, W2s[k * NC2 + c], y[c]);
        }
    }
    float s0 = 0.f, s1 = 0.f, s2 = 0.f;
    #pragma unroll
    for (int c = 0; c < NC2; c++) {
        s0 = fmaf(y[c], att2s[c],           s0);
        s1 = fmaf(y[c], att2s[NC2 + c],     s1);
        s2 = fmaf(y[c], att2s[2 * NC2 + c], s2);
    }
    g_s2[0][n] = s0; g_s2[1][n] = s1; g_s2[2][n] = s2;
    float* xp = g_xp2 + n * 8;
    *(float4*)(xp)     = make_float4(y[0], y[1], y[2], y[3]);
    *(float4*)(xp + 4) = make_float4(y[4], y[5], y[6], 0.f);
}

// ---------------- 5: FUSED layer-2 ------------------------------------------
__global__ void k_fused2() {
    int p = blockIdx.x * blockDim.x + threadIdx.x;
    if (p >= NPATH) return;
    const int s = g_src[p], m = g_mid[p], d = g_dst[p];
    float e = g_s2[0][s] + g_s2[1][m] + g_s2[2][d];
    e = e > 0.f ? e : NEG * e;
    const float w = __expf(e);
    atomicAdd(&g_den2[d], w);
    const float4* xr = (const float4*)(g_xp2 + s * 8);
    float4 v0 = xr[0], v1 = xr[1];
    float* o = g_logits + d * 8;
    red_add_v4(o,     w * v0.x, w * v0.y, w * v0.z, w * v0.w);
    red_add_v4(o + 4, w * v1.x, w * v1.y, w * v1.z, 0.f);
}

// ---------------- 6: normalize, +b2, log_softmax ----------------------------
__global__ void k_final(const float* __restrict__ b2, float* __restrict__ out) {
    int n = blockIdx.x * blockDim.x + threadIdx.x;
    if (n >= NNODES) return;
    const float dinv = 1.f / (g_den2[n] + 1e-16f);
    const float4* lr = (const float4*)(g_logits + n * 8);
    float4 l0 = lr[0], l1 = lr[1];
    float v[NC2] = { l0.x * dinv + __ldg(b2 + 0), l0.y * dinv + __ldg(b2 + 1),
                     l0.z * dinv + __ldg(b2 + 2), l0.w * dinv + __ldg(b2 + 3),
                     l1.x * dinv + __ldg(b2 + 4), l1.y * dinv + __ldg(b2 + 5),
                     l1.z * dinv + __ldg(b2 + 6) };
    float m = v[0];
    #pragma unroll
    for (int c = 1; c < NC2; c++) m = fmaxf(m, v[c]);
    float ssum = 0.f;
    #pragma unroll
    for (int c = 0; c < NC2; c++) ssum += __expf(v[c] - m);
    float ls = logf(ssum) + m;
    #pragma unroll
    for (int c = 0; c < NC2; c++) out[(size_t)n * NC2 + c] = v[c] - ls;
}

// ---------------- launch ----------------------------------------------------
extern "C" void kernel_launch(void* const* d_in, const int* in_sizes, int n_in,
                              void* d_out, int out_size) {
    const float* x    = (const float*)d_in[0];
    const void*  pi   = d_in[1];
    const float* W1   = (const float*)d_in[2];
    const float* att1 = (const float*)d_in[3];
    const float* b1   = (const float*)d_in[4];
    const float* W2   = (const float*)d_in[5];
    const float* att2 = (const float*)d_in[6];
    const float* b2   = (const float*)d_in[7];
    float*       out  = (float*)d_out;

    k_detect<<<1, 1024>>>((const unsigned long long*)pi);
    k_prep<<<(NPATH + 255) / 256, 256>>>(pi);
    k_splitW<<<(FIN * F1 + 255) / 256, 256>>>(W1);
    k_gemm1<<<(NNODES + 127) / 128, 256>>>(x);
    k_score1<<<(NNODES * NH1 + 255) / 256, 256>>>(att1);
    k_fused1<<<(NPATH * NH1 + 255) / 256, 256>>>();
    k_node2<<<(NNODES + 255) / 256, 256>>>(b1, W2, att2);
    k_fused2<<<(NPATH + 255) / 256, 256>>>();
    k_final<<<(NNODES + 255) / 256, 256>>>(b2, out);
}